// round 1
// baseline (speedup 1.0000x reference)
#include <cuda_runtime.h>
#include <cstdint>

// Problem constants
#define BATCH 4
#define CH    64
#define HH    64
#define WW    64
#define QHH   128
#define QWW   128
#define HID   256
#define OUT3  1728      // C*9*3
#define NK    576       // C*9
#define EPSV  1e-6f

// Scratch: pw table transposed: row k (576 rows) x 12 floats [(s=0,o=0..2),(s=1,...),...]
__device__ float g_pwT[NK * 12];

// ---------------------------------------------------------------------------
// Kernel A: evaluate the MLP for the 4 parity classes, write g_pwT.
// grid = 27 blocks (each handles 64 k3 columns for all 4 s), block = 256
// threads (4 j-quarters x 64 columns). w2 is read exactly once chip-wide.
// ---------------------------------------------------------------------------
__global__ void __launch_bounds__(256) mlp_pw_kernel(
    const float* __restrict__ coord, const float* __restrict__ cell,
    const float* __restrict__ w1,    const float* __restrict__ b1,
    const float* __restrict__ w2,    const float* __restrict__ b2)
{
    __shared__ float s_h[4][HID];      // hdd for the 4 parity classes
    __shared__ float s_part[4][64][4]; // [quarter][col][s]

    int tid = threadIdx.x;

    // hdd for all 4 parity classes (each thread computes one hidden unit j=tid)
    {
        int j = tid;
        #pragma unroll
        for (int s = 0; s < 4; ++s) {
            int py = s >> 1, px = s & 1;
            int qs = py * QWW + px;           // representative query (batch 0)
            float cy = coord[qs * 2 + 0];
            float cx = coord[qs * 2 + 1];
            float ly = cell[qs * 2 + 0];
            float lx = cell[qs * 2 + 1];
            float cy_ = cy - ly * 0.5f;
            float cx_ = cx - lx * 0.5f;
            float cqy = fminf(fmaxf(cy_ + EPSV, -1.0f + EPSV), 1.0f - EPSV);
            float cqx = fminf(fmaxf(cx_ + EPSV, -1.0f + EPSV), 1.0f - EPSV);
            float fy = ((cqy + 1.0f) * 64.0f - 1.0f) * 0.5f;
            float fx = ((cqx + 1.0f) * 64.0f - 1.0f) * 0.5f;
            float iy = fminf(fmaxf(rintf(fy), 0.0f), 63.0f);
            float ix = fminf(fmaxf(rintf(fx), 0.0f), 63.0f);
            float qcy = -1.0f + 2.0f * iy / 64.0f;
            float qcx = -1.0f + 2.0f * ix / 64.0f;
            float ry = (cy_ - qcy) * 32.0f;
            float rx = (cx_ - qcx) * 32.0f;
            float rr = ly * 32.0f;
            float h = ry * w1[j] + rx * w1[HID + j] + rr * w1[2 * HID + j] + b1[j];
            s_h[s][j] = fmaxf(h, 0.0f);
        }
    }
    __syncthreads();

    // Each thread: 64 j-iterations, 1 w2 load serves 4 parity classes.
    int col   = tid & 63;                       // 0..63
    int quart = tid >> 6;                       // 0..3
    int k3    = blockIdx.x * 64 + col;          // 0..1727
    int j0    = quart * 64;

    float a0 = 0.f, a1 = 0.f, a2 = 0.f, a3 = 0.f;
    const float* wp = w2 + (size_t)j0 * OUT3 + k3;
    #pragma unroll 8
    for (int j = 0; j < 64; ++j) {
        float w = wp[(size_t)j * OUT3];
        int jj = j0 + j;
        a0 = fmaf(s_h[0][jj], w, a0);
        a1 = fmaf(s_h[1][jj], w, a1);
        a2 = fmaf(s_h[2][jj], w, a2);
        a3 = fmaf(s_h[3][jj], w, a3);
    }
    s_part[quart][col][0] = a0;
    s_part[quart][col][1] = a1;
    s_part[quart][col][2] = a2;
    s_part[quart][col][3] = a3;
    __syncthreads();

    // 256 outputs per block: (col, s)
    int oc = tid >> 2;          // 0..63
    int os = tid & 3;           // 0..3
    int k3o = blockIdx.x * 64 + oc;
    float v = s_part[0][oc][os] + s_part[1][oc][os]
            + s_part[2][oc][os] + s_part[3][oc][os] + b2[k3o];
    int k = k3o / 3;
    int o = k3o - k * 3;
    g_pwT[k * 12 + os * 3 + o] = v;
}

// ---------------------------------------------------------------------------
// f32x2 packed-FMA helpers (FFMA2 — PTX-only on sm_10x)
// ---------------------------------------------------------------------------
__device__ __forceinline__ void ffma2(unsigned long long& d,
                                      unsigned long long a,
                                      unsigned long long b)
{
    asm("fma.rn.f32x2 %0, %1, %2, %0;" : "+l"(d) : "l"(a), "l"(b));
}
__device__ __forceinline__ unsigned long long pack2(float f)
{
    unsigned long long r;
    asm("mov.b64 %0, {%1, %1};" : "=l"(r) : "f"(f));
    return r;
}

// ---------------------------------------------------------------------------
// Kernel B: one thread per LR pixel, handles its 2x2 HR query block (4 queries
// x 3 outputs = 12 accumulators = 6 f32x2).  Block = 128 threads = 16x8 LR
// tile; grid = (4, 8, 4) = 128 blocks.  Feat halo tile (10x18x64) + pw table
// in dynamic smem (73728 B). pw-row loads are warp-uniform (broadcast).
// ---------------------------------------------------------------------------
#define TILE_W 16
#define TILE_H 8
#define HALO_W 18
#define HALO_H 10
#define TILE_ELEMS (CH * HALO_H * HALO_W)   // 11520
#define SMEM_BYTES ((TILE_ELEMS + NK * 12) * 4)

__global__ void __launch_bounds__(128) metasr_main_kernel(
    const float* __restrict__ feat, float* __restrict__ out)
{
    extern __shared__ float smem[];
    float* s_tile = smem;                  // [64][10][18]
    float* s_pw   = smem + TILE_ELEMS;     // [576][12]

    int tid = threadIdx.x;
    int b  = blockIdx.z;
    int Y0 = blockIdx.y * TILE_H;
    int X0 = blockIdx.x * TILE_W;

    // pw table -> smem
    for (int i = tid; i < NK * 12; i += 128) s_pw[i] = g_pwT[i];

    // feat halo tile -> smem (zero-padded at image borders, matching unfold pad=1)
    const float* fb = feat + (size_t)b * CH * HH * WW;
    for (int i = tid; i < TILE_ELEMS; i += 128) {
        int c  = i / (HALO_H * HALO_W);
        int r  = i - c * (HALO_H * HALO_W);
        int yy = r / HALO_W;
        int xx = r - yy * HALO_W;
        int gy = Y0 + yy - 1;
        int gx = X0 + xx - 1;
        float v = 0.0f;
        if ((unsigned)gy < (unsigned)HH && (unsigned)gx < (unsigned)WW)
            v = fb[(c * HH + gy) * WW + gx];
        s_tile[i] = v;
    }
    __syncthreads();

    int lx = tid & 15;
    int ly = tid >> 4;
    const float* tp = s_tile + ly * HALO_W + lx;
    const unsigned long long* pwp = (const unsigned long long*)s_pw;

    unsigned long long acc[6];
    #pragma unroll
    for (int i = 0; i < 6; ++i) acc[i] = 0ull;

    #pragma unroll 2
    for (int c = 0; c < CH; ++c) {
        float f[9];
        #pragma unroll
        for (int dy = 0; dy < 3; ++dy)
            #pragma unroll
            for (int dx = 0; dx < 3; ++dx)
                f[dy * 3 + dx] = tp[c * (HALO_H * HALO_W) + dy * HALO_W + dx];

        #pragma unroll
        for (int t = 0; t < 9; ++t) {
            unsigned long long ff = pack2(f[t]);
            const unsigned long long* p = pwp + (c * 9 + t) * 6;
            #pragma unroll
            for (int i = 0; i < 6; ++i)
                ffma2(acc[i], ff, p[i]);
        }
    }

    // unpack 6 f32x2 -> 12 floats, ordered [s0o0 s0o1 s0o2 s1o0 ... s3o2]
    float res[12];
    #pragma unroll
    for (int i = 0; i < 6; ++i) {
        float xlo, xhi;
        asm("mov.b64 {%0, %1}, %2;" : "=f"(xlo), "=f"(xhi) : "l"(acc[i]));
        res[2 * i]     = xlo;
        res[2 * i + 1] = xhi;
    }

    int Y = Y0 + ly, X = X0 + lx;
    #pragma unroll
    for (int s = 0; s < 4; ++s) {
        int py = s >> 1, px = s & 1;
        int yq = 2 * Y + py;
        int xq = 2 * X + px;
        int base = ((b * QHH + yq) * QWW + xq) * 3;
        out[base + 0] = res[s * 3 + 0];
        out[base + 1] = res[s * 3 + 1];
        out[base + 2] = res[s * 3 + 2];
    }
}

// ---------------------------------------------------------------------------
extern "C" void kernel_launch(void* const* d_in, const int* in_sizes, int n_in,
                              void* d_out, int out_size)
{
    const float* feat  = (const float*)d_in[0];
    const float* coord = (const float*)d_in[1];
    const float* cell  = (const float*)d_in[2];
    const float* w1    = (const float*)d_in[3];
    const float* b1    = (const float*)d_in[4];
    const float* w2    = (const float*)d_in[5];
    const float* b2    = (const float*)d_in[6];
    float* out = (float*)d_out;

    cudaFuncSetAttribute(metasr_main_kernel,
                         cudaFuncAttributeMaxDynamicSharedMemorySize, SMEM_BYTES);

    mlp_pw_kernel<<<27, 256>>>(coord, cell, w1, b1, w2, b2);

    dim3 grid(WW / TILE_W, HH / TILE_H, BATCH);  // (4, 8, 4)
    metasr_main_kernel<<<grid, 128, SMEM_BYTES>>>(feat, out);
}

// round 2
// speedup vs baseline: 1.6652x; 1.6652x over previous
#include <cuda_runtime.h>
#include <cstdint>

// Problem constants
#define BATCH 4
#define CH    64
#define HH    64
#define WW    64
#define QHH   128
#define QWW   128
#define HID   256
#define OUT3  1728      // C*9*3
#define NK    576       // C*9
#define EPSV  1e-6f

// pw table, transposed: row k (576) x 12 floats [s0o0 s0o1 s0o2 s1o0 ... s3o2]
__device__ float g_pwT[NK * 12];

// ---------------------------------------------------------------------------
// Kernel A0: seed g_pwT with b2 (overwrites previous replay's accumulation).
// ---------------------------------------------------------------------------
__global__ void pw_init_kernel(const float* __restrict__ b2)
{
    int idx = blockIdx.x * 256 + threadIdx.x;   // 0..6911
    int k = idx / 12;
    int r = idx - k * 12;
    int o = r % 3;
    g_pwT[idx] = b2[k * 3 + o];
}

// ---------------------------------------------------------------------------
// Kernel A1: MLP for the 4 parity classes, accumulated into g_pwT.
// grid = (27, 8): x = 64-column tile of OUT3, y = 32-wide j-slice of HID.
// block = 256 threads (64 cols x 4 j-subslices of 8). w2 read once chip-wide.
// ---------------------------------------------------------------------------
__global__ void __launch_bounds__(256) mlp_pw_kernel(
    const float* __restrict__ coord, const float* __restrict__ cell,
    const float* __restrict__ w1,    const float* __restrict__ b1,
    const float* __restrict__ w2)
{
    __shared__ float s_h[4][HID];      // hdd for the 4 parity classes
    __shared__ float s_part[4][64][4]; // [jsub][col][s]

    int tid = threadIdx.x;

    // hdd for all 4 parity classes (thread computes hidden unit j=tid)
    {
        int j = tid;
        #pragma unroll
        for (int s = 0; s < 4; ++s) {
            int py = s >> 1, px = s & 1;
            int qs = py * QWW + px;           // representative query (batch 0)
            float cy = coord[qs * 2 + 0];
            float cx = coord[qs * 2 + 1];
            float ly = cell[qs * 2 + 0];
            float lx = cell[qs * 2 + 1];
            float cy_ = cy - ly * 0.5f;
            float cx_ = cx - lx * 0.5f;
            float cqy = fminf(fmaxf(cy_ + EPSV, -1.0f + EPSV), 1.0f - EPSV);
            float cqx = fminf(fmaxf(cx_ + EPSV, -1.0f + EPSV), 1.0f - EPSV);
            float fy = ((cqy + 1.0f) * 64.0f - 1.0f) * 0.5f;
            float fx = ((cqx + 1.0f) * 64.0f - 1.0f) * 0.5f;
            float iy = fminf(fmaxf(rintf(fy), 0.0f), 63.0f);
            float ix = fminf(fmaxf(rintf(fx), 0.0f), 63.0f);
            float qcy = -1.0f + 2.0f * iy / 64.0f;
            float qcx = -1.0f + 2.0f * ix / 64.0f;
            float ry = (cy_ - qcy) * 32.0f;
            float rx = (cx_ - qcx) * 32.0f;
            float rr = ly * 32.0f;
            float h = ry * w1[j] + rx * w1[HID + j] + rr * w1[2 * HID + j] + b1[j];
            s_h[s][j] = fmaxf(h, 0.0f);
        }
    }
    __syncthreads();

    int col  = tid & 63;                        // 0..63
    int jsub = tid >> 6;                        // 0..3
    int k3   = blockIdx.x * 64 + col;           // 0..1727
    int j0   = blockIdx.y * 32 + jsub * 8;

    float a0 = 0.f, a1 = 0.f, a2 = 0.f, a3 = 0.f;
    const float* wp = w2 + (size_t)j0 * OUT3 + k3;
    #pragma unroll
    for (int j = 0; j < 8; ++j) {
        float w = wp[(size_t)j * OUT3];
        int jj = j0 + j;
        a0 = fmaf(s_h[0][jj], w, a0);
        a1 = fmaf(s_h[1][jj], w, a1);
        a2 = fmaf(s_h[2][jj], w, a2);
        a3 = fmaf(s_h[3][jj], w, a3);
    }
    s_part[jsub][col][0] = a0;
    s_part[jsub][col][1] = a1;
    s_part[jsub][col][2] = a2;
    s_part[jsub][col][3] = a3;
    __syncthreads();

    int oc = tid >> 2;          // 0..63
    int os = tid & 3;           // 0..3
    int k3o = blockIdx.x * 64 + oc;
    float v = s_part[0][oc][os] + s_part[1][oc][os]
            + s_part[2][oc][os] + s_part[3][oc][os];
    int k = k3o / 3;
    int o = k3o - k * 3;
    atomicAdd(&g_pwT[k * 12 + os * 3 + o], v);
}

// ---------------------------------------------------------------------------
// f32x2 packed helpers (FFMA2 — PTX-only on sm_10x)
// ---------------------------------------------------------------------------
__device__ __forceinline__ void ffma2(unsigned long long& d,
                                      unsigned long long a,
                                      unsigned long long b)
{
    asm("fma.rn.f32x2 %0, %1, %2, %0;" : "+l"(d) : "l"(a), "l"(b));
}
__device__ __forceinline__ void addf2(unsigned long long& d, unsigned long long a)
{
    asm("add.rn.f32x2 %0, %0, %1;" : "+l"(d) : "l"(a));
}
__device__ __forceinline__ unsigned long long pack2(float f)
{
    unsigned long long r;
    asm("mov.b64 %0, {%1, %1};" : "=l"(r) : "f"(f));
    return r;
}

// ---------------------------------------------------------------------------
// Kernel B: GEMM-style. Block = 256 threads (8 warps), covers 2 LR rows
// (128 pixels). k-dim (576 = 64ch x 9taps) split across the 8 warps (72 k
// each, = 8 channels). Each lane owns 4 pixels x 12 outputs (24 f32x2 accs).
// Per k: 4 conflict-free feat LDS + 3 warp-uniform pw LDS.128 + 24 FFMA2.
// Cross-warp reduction via smem, then store.
// ---------------------------------------------------------------------------
#define TROWS 4
#define TW    66
#define CS    (TROWS * TW)          // 264 words per channel
#define TILE_WORDS (CH * CS)        // 16896
#define PW_WORDS   (NK * 12)        // 6912
#define SMEM_B ((TILE_WORDS + PW_WORDS) * 4)   // 95232 bytes

__global__ void __launch_bounds__(256) metasr_main_kernel(
    const float* __restrict__ feat, float* __restrict__ out)
{
    extern __shared__ float smem[];
    float* s_tile = smem;
    float* s_pw   = smem + TILE_WORDS;

    int tid = threadIdx.x;
    int bx  = blockIdx.x;            // 0..127
    int b   = bx >> 5;
    int y0  = (bx & 31) * 2;         // first of the 2 LR rows

    // ---- pw table -> smem ----
    for (int i = tid; i < PW_WORDS; i += 256) s_pw[i] = g_pwT[i];

    // ---- halo columns (x = -1 and x = 64 are always out of bounds) ----
    for (int i = tid; i < CH * TROWS; i += 256) {
        int c = i >> 2, r = i & 3;
        s_tile[c * CS + r * TW + 0]  = 0.0f;
        s_tile[c * CS + r * TW + 65] = 0.0f;
    }

    // ---- interior: full-width rows via float4 ----
    const float* fb = feat + (size_t)b * CH * HH * WW;
    for (int i = tid; i < CH * TROWS * 16; i += 256) {
        int c   = i >> 6;
        int rr  = (i >> 4) & 3;
        int xq4 = i & 15;
        int y   = y0 - 1 + rr;
        float4 v = make_float4(0.f, 0.f, 0.f, 0.f);
        if ((unsigned)y < 64u)
            v = *(const float4*)(fb + ((c << 6) + y) * 64 + xq4 * 4);
        float* dst = s_tile + c * CS + rr * TW + 1 + xq4 * 4;
        dst[0] = v.x; dst[1] = v.y; dst[2] = v.z; dst[3] = v.w;
    }
    __syncthreads();

    // ---- main loop ----
    int w    = tid >> 5;
    int lane = tid & 31;

    // lane's 4 pixels: p = lane + 32*pix; tile offsets (pixel at tile row
    // (p>>6)+1, col (p&63)+1; tap (dy,dx) reads row (p>>6)+dy, col (p&63)+dx)
    int o0 = lane;                 // pix 0: row 0 base
    int o1 = lane + 32;            // pix 1
    int o2 = TW + lane;            // pix 2: row 1 base
    int o3 = TW + lane + 32;       // pix 3

    const float* tbase = s_tile + (w << 3) * CS;               // warp's channels
    const ulonglong2* pwb = (const ulonglong2*)s_pw + (w * 72) * 3;

    unsigned long long acc[24];
    #pragma unroll
    for (int i = 0; i < 24; ++i) acc[i] = 0ull;

    for (int cc = 0; cc < 8; ++cc) {
        const float* tc = tbase + cc * CS;
        const ulonglong2* pk = pwb + cc * 27;   // 9 taps * 3 ull2
        #pragma unroll
        for (int t = 0; t < 9; ++t) {
            int doff = (t / 3) * TW + (t % 3);
            float f0 = tc[o0 + doff];
            float f1 = tc[o1 + doff];
            float f2 = tc[o2 + doff];
            float f3 = tc[o3 + doff];
            ulonglong2 p01 = pk[t * 3 + 0];
            ulonglong2 p23 = pk[t * 3 + 1];
            ulonglong2 p45 = pk[t * 3 + 2];
            unsigned long long F0 = pack2(f0);
            unsigned long long F1 = pack2(f1);
            unsigned long long F2 = pack2(f2);
            unsigned long long F3 = pack2(f3);
            ffma2(acc[0],  F0, p01.x); ffma2(acc[1],  F0, p01.y);
            ffma2(acc[2],  F0, p23.x); ffma2(acc[3],  F0, p23.y);
            ffma2(acc[4],  F0, p45.x); ffma2(acc[5],  F0, p45.y);
            ffma2(acc[6],  F1, p01.x); ffma2(acc[7],  F1, p01.y);
            ffma2(acc[8],  F1, p23.x); ffma2(acc[9],  F1, p23.y);
            ffma2(acc[10], F1, p45.x); ffma2(acc[11], F1, p45.y);
            ffma2(acc[12], F2, p01.x); ffma2(acc[13], F2, p01.y);
            ffma2(acc[14], F2, p23.x); ffma2(acc[15], F2, p23.y);
            ffma2(acc[16], F2, p45.x); ffma2(acc[17], F2, p45.y);
            ffma2(acc[18], F3, p01.x); ffma2(acc[19], F3, p01.y);
            ffma2(acc[20], F3, p23.x); ffma2(acc[21], F3, p23.y);
            ffma2(acc[22], F3, p45.x); ffma2(acc[23], F3, p45.y);
        }
    }

    // ---- cross-warp reduction: s_red[w][i(24)][lane] (64-bit, conflict-free)
    __syncthreads();
    unsigned long long* s_red = (unsigned long long*)smem;
    #pragma unroll
    for (int i = 0; i < 24; ++i)
        s_red[(w * 24 + i) * 32 + lane] = acc[i];
    __syncthreads();

    // pass 2: 768 output ull; thread -> (pixel p = tid>>1, half h = tid&1)
    int p   = tid >> 1;
    int hf  = tid & 1;
    int pix = p >> 5;
    int L   = p & 31;

    float r6[6];
    #pragma unroll
    for (int i = 0; i < 3; ++i) {
        int srcidx = pix * 6 + hf * 3 + i;
        unsigned long long v = s_red[(0 * 24 + srcidx) * 32 + L];
        #pragma unroll
        for (int ww = 1; ww < 8; ++ww)
            addf2(v, s_red[(ww * 24 + srcidx) * 32 + L]);
        float xlo, xhi;
        asm("mov.b64 {%0, %1}, %2;" : "=f"(xlo), "=f"(xhi) : "l"(v));
        r6[2 * i]     = xlo;
        r6[2 * i + 1] = xhi;
    }

    // write: hf==0 -> parity classes s=0,1 ; hf==1 -> s=2,3
    int y = y0 + (p >> 6);
    int x = p & 63;
    #pragma unroll
    for (int si = 0; si < 2; ++si) {
        int s = hf * 2 + si;
        int py = s >> 1, px = s & 1;
        int yq = 2 * y + py;
        int xq = 2 * x + px;
        int base = ((b * QHH + yq) * QWW + xq) * 3;
        out[base + 0] = r6[si * 3 + 0];
        out[base + 1] = r6[si * 3 + 1];
        out[base + 2] = r6[si * 3 + 2];
    }
}

// ---------------------------------------------------------------------------
extern "C" void kernel_launch(void* const* d_in, const int* in_sizes, int n_in,
                              void* d_out, int out_size)
{
    const float* feat  = (const float*)d_in[0];
    const float* coord = (const float*)d_in[1];
    const float* cell  = (const float*)d_in[2];
    const float* w1    = (const float*)d_in[3];
    const float* b1    = (const float*)d_in[4];
    const float* w2    = (const float*)d_in[5];
    const float* b2    = (const float*)d_in[6];
    float* out = (float*)d_out;

    cudaFuncSetAttribute(metasr_main_kernel,
                         cudaFuncAttributeMaxDynamicSharedMemorySize, SMEM_B);

    pw_init_kernel<<<27, 256>>>(b2);

    dim3 gA(27, 8);
    mlp_pw_kernel<<<gA, 256>>>(coord, cell, w1, b1, w2);

    metasr_main_kernel<<<128, 256, SMEM_B>>>(feat, out);
}

// round 3
// speedup vs baseline: 1.8431x; 1.1068x over previous
#include <cuda_runtime.h>
#include <cstdint>

// Problem constants
#define BATCH 4
#define CH    64
#define HH    64
#define WW    64
#define QHH   128
#define QWW   128
#define HID   256
#define OUT3  1728      // C*9*3
#define NK    576       // C*9
#define EPSV  1e-6f

// pw table, transposed: row k (576) x 12 floats [s0o0 s0o1 s0o2 s1o0 ... s3o2]
__device__ float g_pwT[NK * 12];

// ---------------------------------------------------------------------------
// Kernel A: MLP for the 4 parity classes -> g_pwT. Atomic-free, init-free.
// grid = 108 blocks; each block owns 16 OUT3-columns and reduces the FULL
// j = 0..255 range internally (16 jsubs x 16 j). b2 added at final write.
// ---------------------------------------------------------------------------
__global__ void __launch_bounds__(256) mlp_pw_kernel(
    const float* __restrict__ coord, const float* __restrict__ cell,
    const float* __restrict__ w1,    const float* __restrict__ b1,
    const float* __restrict__ w2,    const float* __restrict__ b2)
{
    __shared__ float s_h[4][HID];        // hdd for the 4 parity classes
    __shared__ float s_part[16][16][4];  // [jsub][col][s]

    int tid = threadIdx.x;

    // hdd for all 4 parity classes (thread computes hidden unit j = tid)
    {
        int j = tid;
        #pragma unroll
        for (int s = 0; s < 4; ++s) {
            int py = s >> 1, px = s & 1;
            int qs = py * QWW + px;           // representative query (batch 0)
            float cy = coord[qs * 2 + 0];
            float cx = coord[qs * 2 + 1];
            float ly = cell[qs * 2 + 0];
            float lx = cell[qs * 2 + 1];
            float cy_ = cy - ly * 0.5f;
            float cx_ = cx - lx * 0.5f;
            float cqy = fminf(fmaxf(cy_ + EPSV, -1.0f + EPSV), 1.0f - EPSV);
            float cqx = fminf(fmaxf(cx_ + EPSV, -1.0f + EPSV), 1.0f - EPSV);
            float fy = ((cqy + 1.0f) * 64.0f - 1.0f) * 0.5f;
            float fx = ((cqx + 1.0f) * 64.0f - 1.0f) * 0.5f;
            float iy = fminf(fmaxf(rintf(fy), 0.0f), 63.0f);
            float ix = fminf(fmaxf(rintf(fx), 0.0f), 63.0f);
            float qcy = -1.0f + 2.0f * iy / 64.0f;
            float qcx = -1.0f + 2.0f * ix / 64.0f;
            float ry = (cy_ - qcy) * 32.0f;
            float rx = (cx_ - qcx) * 32.0f;
            float rr = ly * 32.0f;
            float h = ry * w1[j] + rx * w1[HID + j] + rr * w1[2 * HID + j] + b1[j];
            s_h[s][j] = fmaxf(h, 0.0f);
        }
    }
    __syncthreads();

    int col  = tid & 15;                        // 0..15
    int jsub = tid >> 4;                        // 0..15
    int k3   = blockIdx.x * 16 + col;           // 0..1727
    int j0   = jsub * 16;

    float a0 = 0.f, a1 = 0.f, a2 = 0.f, a3 = 0.f;
    const float* wp = w2 + (size_t)j0 * OUT3 + k3;
    #pragma unroll
    for (int j = 0; j < 16; ++j) {
        float w = wp[(size_t)j * OUT3];
        int jj = j0 + j;
        a0 = fmaf(s_h[0][jj], w, a0);
        a1 = fmaf(s_h[1][jj], w, a1);
        a2 = fmaf(s_h[2][jj], w, a2);
        a3 = fmaf(s_h[3][jj], w, a3);
    }
    s_part[jsub][col][0] = a0;
    s_part[jsub][col][1] = a1;
    s_part[jsub][col][2] = a2;
    s_part[jsub][col][3] = a3;
    __syncthreads();

    if (tid < 64) {
        int oc = tid >> 2;          // 0..15
        int os = tid & 3;           // 0..3
        int k3o = blockIdx.x * 16 + oc;
        float v = b2[k3o];
        #pragma unroll
        for (int t = 0; t < 16; ++t) v += s_part[t][oc][os];
        int k = k3o / 3;
        int o = k3o - k * 3;
        g_pwT[k * 12 + os * 3 + o] = v;
    }
}

// ---------------------------------------------------------------------------
// f32x2 packed helpers (FFMA2 — PTX-only on sm_10x)
// ---------------------------------------------------------------------------
__device__ __forceinline__ void ffma2(unsigned long long& d,
                                      unsigned long long a,
                                      unsigned long long b)
{
    asm("fma.rn.f32x2 %0, %1, %2, %0;" : "+l"(d) : "l"(a), "l"(b));
}
__device__ __forceinline__ void addf2(unsigned long long& d, unsigned long long a)
{
    asm("add.rn.f32x2 %0, %0, %1;" : "+l"(d) : "l"(a));
}

// ---------------------------------------------------------------------------
// Kernel B: GEMM-style contraction. Block = 256 threads (8 warps), covers 2
// LR rows (128 pixels). k (576 = 64ch x 9taps) split across 8 warps. Each
// lane: 4 pixels x 12 outputs = 24 f32x2 accumulators.
// Feat tile stored DUPLICATED ((f,f) pairs) so each feat operand is a single
// LDS.64 with no mov/pack. pw rows are warp-uniform LDS.128 broadcasts.
// Per tap per lane: 4 LDS.64 + 3 LDS.128(uniform) + 24 FFMA2.
// ---------------------------------------------------------------------------
#define TROWS 4
#define TW    66
#define CS2   (TROWS * TW)              // 264 float2 per channel
#define TILE2_WORDS (CH * CS2 * 2)      // 33792 floats (135168 B)
#define PW_WORDS    (NK * 12)           // 6912 floats  (27648 B)
#define SMEM_B ((TILE2_WORDS + PW_WORDS) * 4)   // 162816 bytes

__global__ void __launch_bounds__(256) metasr_main_kernel(
    const float* __restrict__ feat, float* __restrict__ out)
{
    extern __shared__ float smem[];
    float2* s_tile2 = (float2*)smem;            // [64][4][66] duplicated pairs
    float*  s_pw    = smem + TILE2_WORDS;       // [576][12]

    int tid = threadIdx.x;
    int bx  = blockIdx.x;            // 0..127
    int b   = bx >> 5;
    int y0  = (bx & 31) * 2;         // first of the 2 LR rows

    // ---- pw table -> smem ----
    for (int i = tid; i < PW_WORDS; i += 256) s_pw[i] = g_pwT[i];

    // ---- halo columns (x = -1 and x = 64 are always out of bounds) ----
    for (int i = tid; i < CH * TROWS; i += 256) {
        int c = i >> 2, r = i & 3;
        s_tile2[c * CS2 + r * TW + 0]  = make_float2(0.f, 0.f);
        s_tile2[c * CS2 + r * TW + 65] = make_float2(0.f, 0.f);
    }

    // ---- interior: full-width rows via float4, stored duplicated ----
    const float* fb = feat + (size_t)b * CH * HH * WW;
    for (int i = tid; i < CH * TROWS * 16; i += 256) {
        int c   = i >> 6;
        int rr  = (i >> 4) & 3;
        int xq4 = i & 15;
        int y   = y0 - 1 + rr;
        float4 v = make_float4(0.f, 0.f, 0.f, 0.f);
        if ((unsigned)y < 64u)
            v = *(const float4*)(fb + ((c << 6) + y) * 64 + xq4 * 4);
        float2* dst = s_tile2 + c * CS2 + rr * TW + 1 + xq4 * 4;
        dst[0] = make_float2(v.x, v.x);
        dst[1] = make_float2(v.y, v.y);
        dst[2] = make_float2(v.z, v.z);
        dst[3] = make_float2(v.w, v.w);
    }
    __syncthreads();

    // ---- main loop ----
    int w    = tid >> 5;
    int lane = tid & 31;

    // lane's 4 pixels (float2/ull units): p = lane + 32*pix
    int o0 = lane;                 // pix 0: tile row 0 base
    int o1 = lane + 32;            // pix 1
    int o2 = TW + lane;            // pix 2: tile row 1 base
    int o3 = TW + lane + 32;       // pix 3

    const unsigned long long* tw8 =
        (const unsigned long long*)s_tile2 + (w << 3) * CS2;  // warp's 8 channels
    const ulonglong2* pwb = (const ulonglong2*)s_pw + (w * 72) * 3;

    unsigned long long acc[24];
    #pragma unroll
    for (int i = 0; i < 24; ++i) acc[i] = 0ull;

    #pragma unroll
    for (int cc = 0; cc < 8; ++cc) {
        const unsigned long long* tc = tw8 + cc * CS2;
        const ulonglong2* pk = pwb + cc * 27;   // 9 taps * 3 ull2
        #pragma unroll
        for (int t = 0; t < 9; ++t) {
            const int doff = (t / 3) * TW + (t % 3);
            unsigned long long F0 = tc[o0 + doff];
            unsigned long long F1 = tc[o1 + doff];
            unsigned long long F2 = tc[o2 + doff];
            unsigned long long F3 = tc[o3 + doff];
            ulonglong2 p01 = pk[t * 3 + 0];
            ulonglong2 p23 = pk[t * 3 + 1];
            ulonglong2 p45 = pk[t * 3 + 2];
            ffma2(acc[0],  F0, p01.x); ffma2(acc[1],  F0, p01.y);
            ffma2(acc[2],  F0, p23.x); ffma2(acc[3],  F0, p23.y);
            ffma2(acc[4],  F0, p45.x); ffma2(acc[5],  F0, p45.y);
            ffma2(acc[6],  F1, p01.x); ffma2(acc[7],  F1, p01.y);
            ffma2(acc[8],  F1, p23.x); ffma2(acc[9],  F1, p23.y);
            ffma2(acc[10], F1, p45.x); ffma2(acc[11], F1, p45.y);
            ffma2(acc[12], F2, p01.x); ffma2(acc[13], F2, p01.y);
            ffma2(acc[14], F2, p23.x); ffma2(acc[15], F2, p23.y);
            ffma2(acc[16], F2, p45.x); ffma2(acc[17], F2, p45.y);
            ffma2(acc[18], F3, p01.x); ffma2(acc[19], F3, p01.y);
            ffma2(acc[20], F3, p23.x); ffma2(acc[21], F3, p23.y);
            ffma2(acc[22], F3, p45.x); ffma2(acc[23], F3, p45.y);
        }
    }

    // ---- cross-warp reduction: s_red[w][i(24)][lane] (64-bit, conflict-free)
    __syncthreads();
    unsigned long long* s_red = (unsigned long long*)smem;
    #pragma unroll
    for (int i = 0; i < 24; ++i)
        s_red[(w * 24 + i) * 32 + lane] = acc[i];
    __syncthreads();

    // pass 2: 768 output ull; thread -> (pixel p = tid>>1, half h = tid&1)
    int p   = tid >> 1;
    int hf  = tid & 1;
    int pix = p >> 5;
    int L   = p & 31;

    float r6[6];
    #pragma unroll
    for (int i = 0; i < 3; ++i) {
        int srcidx = pix * 6 + hf * 3 + i;
        unsigned long long v = s_red[(0 * 24 + srcidx) * 32 + L];
        #pragma unroll
        for (int ww = 1; ww < 8; ++ww)
            addf2(v, s_red[(ww * 24 + srcidx) * 32 + L]);
        float xlo, xhi;
        asm("mov.b64 {%0, %1}, %2;" : "=f"(xlo), "=f"(xhi) : "l"(v));
        r6[2 * i]     = xlo;
        r6[2 * i + 1] = xhi;
    }

    // write: hf==0 -> parity classes s=0,1 ; hf==1 -> s=2,3
    int y = y0 + (p >> 6);
    int x = p & 63;
    #pragma unroll
    for (int si = 0; si < 2; ++si) {
        int s = hf * 2 + si;
        int py = s >> 1, px = s & 1;
        int yq = 2 * y + py;
        int xq = 2 * x + px;
        int base = ((b * QHH + yq) * QWW + xq) * 3;
        out[base + 0] = r6[si * 3 + 0];
        out[base + 1] = r6[si * 3 + 1];
        out[base + 2] = r6[si * 3 + 2];
    }
}

// ---------------------------------------------------------------------------
extern "C" void kernel_launch(void* const* d_in, const int* in_sizes, int n_in,
                              void* d_out, int out_size)
{
    const float* feat  = (const float*)d_in[0];
    const float* coord = (const float*)d_in[1];
    const float* cell  = (const float*)d_in[2];
    const float* w1    = (const float*)d_in[3];
    const float* b1    = (const float*)d_in[4];
    const float* w2    = (const float*)d_in[5];
    const float* b2    = (const float*)d_in[6];
    float* out = (float*)d_out;

    cudaFuncSetAttribute(metasr_main_kernel,
                         cudaFuncAttributeMaxDynamicSharedMemorySize, SMEM_B);

    mlp_pw_kernel<<<108, 256>>>(coord, cell, w1, b1, w2, b2);
    metasr_main_kernel<<<128, 256, SMEM_B>>>(feat, out);
}